// round 6
// baseline (speedup 1.0000x reference)
#include <cuda_runtime.h>
#include <math.h>
#include <stdint.h>

#define BATCH 4
#define C 64
#define HH 256
#define WW 256
#define NPIX (HH*WW)
#define NHEADS 8
#define NTILE 64              // row tiles (4 rows each) = NCHUNK for partials
#define PITCH 136             // smem row pitch (floats) in gemm kernels

// ---------------- scratch (static device globals) ----------------
__device__ float g_midQ[BATCH*C*NPIX];
__device__ float g_midK[BATCH*C*NPIX];
__device__ float g_midV[BATCH*C*NPIX];
__device__ float g_V[BATCH*C*NPIX];
__device__ float g_part[BATCH*NHEADS*NTILE*80];
__device__ float g_attn[BATCH*NHEADS*64];
__device__ float g_weff[BATCH*C*C];

__device__ __forceinline__ uint32_t f2tf32(float v){
    uint32_t t; asm("cvt.rna.tf32.f32 %0, %1;" : "=r"(t) : "f"(v)); return t;
}

#define MMA_TF32(c0,c1,c2,c3,a0,a1,a2,a3,b0,b1) \
  asm volatile("mma.sync.aligned.m16n8k8.row.col.f32.tf32.tf32.f32 " \
    "{%0,%1,%2,%3}, {%4,%5,%6,%7}, {%8,%9}, {%0,%1,%2,%3};" \
    : "+f"(c0),"+f"(c1),"+f"(c2),"+f"(c3) \
    : "r"(a0),"r"(a1),"r"(a2),"r"(a3),"r"(b0),"r"(b1))

// ============ gemm_mma: out[co][px] = sum_ci w[co][ci]*in[ci][px], 64 out ch ===
__global__ void __launch_bounds__(128) gemm_mma(
    const float* __restrict__ in, const float* __restrict__ w,
    float* __restrict__ out, int w_per_batch)
{
    extern __shared__ float sm[];              // [2][64][PITCH]
    float* s_hi = sm;
    float* s_lo = sm + 64*PITCH;

    const int tid  = threadIdx.x;
    const int lane = tid & 31, warp = tid >> 5;
    const int b    = blockIdx.y;
    const int px0  = blockIdx.x * 128;
    const int gid  = lane >> 2, tig = lane & 3;

    const float* wb = w + (w_per_batch ? b*C*C : 0);
    uint32_t Ah[8][4], Al[8][4];
    const int co_r0 = warp*16 + gid;
    #pragma unroll
    for (int kc = 0; kc < 8; kc++) {
        #pragma unroll
        for (int j = 0; j < 4; j++) {
            const int row = co_r0 + (j & 1)*8;
            const int col = kc*8 + tig + (j >> 1)*4;
            const float x = __ldg(wb + row*C + col);
            const uint32_t h = f2tf32(x);
            Ah[kc][j] = h;
            Al[kc][j] = f2tf32(x - __uint_as_float(h));
        }
    }

    const float* ib = in + (size_t)b*(C*NPIX) + px0;
    #pragma unroll
    for (int i = 0; i < 16; i++) {
        const int ci = warp + 4*i;
        const float4 v = *(const float4*)(ib + (size_t)ci*NPIX + lane*4);
        uint32_t h0 = f2tf32(v.x), h1 = f2tf32(v.y);
        uint32_t h2 = f2tf32(v.z), h3 = f2tf32(v.w);
        uint32_t l0 = f2tf32(v.x - __uint_as_float(h0));
        uint32_t l1 = f2tf32(v.y - __uint_as_float(h1));
        uint32_t l2 = f2tf32(v.z - __uint_as_float(h2));
        uint32_t l3 = f2tf32(v.w - __uint_as_float(h3));
        *(uint4*)(s_hi + ci*PITCH + lane*4) = make_uint4(h0, h1, h2, h3);
        *(uint4*)(s_lo + ci*PITCH + lane*4) = make_uint4(l0, l1, l2, l3);
    }
    __syncthreads();

    float* ob = out + (size_t)b*(C*NPIX) + px0;
    const int co_base = warp*16;
    #pragma unroll 2
    for (int nt = 0; nt < 16; nt++) {
        float c0 = 0.f, c1 = 0.f, c2 = 0.f, c3 = 0.f;
        const int pxl = nt*8 + gid;
        #pragma unroll
        for (int kc = 0; kc < 8; kc++) {
            const int r0 = (kc*8 + tig)*PITCH + pxl;
            const int r1 = r0 + 4*PITCH;
            const uint32_t b0h = __float_as_uint(s_hi[r0]);
            const uint32_t b1h = __float_as_uint(s_hi[r1]);
            const uint32_t b0l = __float_as_uint(s_lo[r0]);
            const uint32_t b1l = __float_as_uint(s_lo[r1]);
            MMA_TF32(c0,c1,c2,c3, Ah[kc][0],Ah[kc][1],Ah[kc][2],Ah[kc][3], b0h,b1h);
            MMA_TF32(c0,c1,c2,c3, Ah[kc][0],Ah[kc][1],Ah[kc][2],Ah[kc][3], b0l,b1l);
            MMA_TF32(c0,c1,c2,c3, Al[kc][0],Al[kc][1],Al[kc][2],Al[kc][3], b0h,b1h);
        }
        const int pxs = nt*8 + tig*2;
        *(float2*)(ob + (size_t)(co_base+gid  )*NPIX + pxs) = make_float2(c0, c1);
        *(float2*)(ob + (size_t)(co_base+gid+8)*NPIX + pxs) = make_float2(c2, c3);
    }
}

// ======== gemm_mma_kv: 128 output channels (K then V), input staged once ======
__global__ void __launch_bounds__(256) gemm_mma_kv(
    const float* __restrict__ in, const float* __restrict__ w,
    float* __restrict__ outK, float* __restrict__ outV)
{
    extern __shared__ float sm[];
    float* s_hi = sm;
    float* s_lo = sm + 64*PITCH;

    const int tid  = threadIdx.x;
    const int lane = tid & 31, warp = tid >> 5;   // 8 warps
    const int b    = blockIdx.y;
    const int px0  = blockIdx.x * 128;
    const int gid  = lane >> 2, tig = lane & 3;

    uint32_t Ah[8][4], Al[8][4];
    const int co_r0 = warp*16 + gid;              // 0..127
    #pragma unroll
    for (int kc = 0; kc < 8; kc++) {
        #pragma unroll
        for (int j = 0; j < 4; j++) {
            const int row = co_r0 + (j & 1)*8;
            const int col = kc*8 + tig + (j >> 1)*4;
            const float x = __ldg(w + row*C + col);
            const uint32_t h = f2tf32(x);
            Ah[kc][j] = h;
            Al[kc][j] = f2tf32(x - __uint_as_float(h));
        }
    }

    const float* ib = in + (size_t)b*(C*NPIX) + px0;
    #pragma unroll
    for (int i = 0; i < 8; i++) {
        const int ci = warp + 8*i;
        const float4 v = *(const float4*)(ib + (size_t)ci*NPIX + lane*4);
        uint32_t h0 = f2tf32(v.x), h1 = f2tf32(v.y);
        uint32_t h2 = f2tf32(v.z), h3 = f2tf32(v.w);
        uint32_t l0 = f2tf32(v.x - __uint_as_float(h0));
        uint32_t l1 = f2tf32(v.y - __uint_as_float(h1));
        uint32_t l2 = f2tf32(v.z - __uint_as_float(h2));
        uint32_t l3 = f2tf32(v.w - __uint_as_float(h3));
        *(uint4*)(s_hi + ci*PITCH + lane*4) = make_uint4(h0, h1, h2, h3);
        *(uint4*)(s_lo + ci*PITCH + lane*4) = make_uint4(l0, l1, l2, l3);
    }
    __syncthreads();

    const int co_base = warp*16;                  // 0..112
    float* ob = ((co_base < 64) ? outK : outV) + (size_t)b*(C*NPIX) + px0;
    const int co_loc = co_base & 63;
    #pragma unroll 2
    for (int nt = 0; nt < 16; nt++) {
        float c0 = 0.f, c1 = 0.f, c2 = 0.f, c3 = 0.f;
        const int pxl = nt*8 + gid;
        #pragma unroll
        for (int kc = 0; kc < 8; kc++) {
            const int r0 = (kc*8 + tig)*PITCH + pxl;
            const int r1 = r0 + 4*PITCH;
            const uint32_t b0h = __float_as_uint(s_hi[r0]);
            const uint32_t b1h = __float_as_uint(s_hi[r1]);
            const uint32_t b0l = __float_as_uint(s_lo[r0]);
            const uint32_t b1l = __float_as_uint(s_lo[r1]);
            MMA_TF32(c0,c1,c2,c3, Ah[kc][0],Ah[kc][1],Ah[kc][2],Ah[kc][3], b0h,b1h);
            MMA_TF32(c0,c1,c2,c3, Ah[kc][0],Ah[kc][1],Ah[kc][2],Ah[kc][3], b0l,b1l);
            MMA_TF32(c0,c1,c2,c3, Al[kc][0],Al[kc][1],Al[kc][2],Al[kc][3], b0h,b1h);
        }
        const int pxs = nt*8 + tig*2;
        *(float2*)(ob + (size_t)(co_loc+gid  )*NPIX + pxs) = make_float2(c0, c1);
        *(float2*)(ob + (size_t)(co_loc+gid+8)*NPIX + pxs) = make_float2(c2, c3);
    }
}

// ============ dwqk_attn: dw3x3(midQ), dw3x3(midK) -> smem -> partial dots =====
// Block = (row-tile of 4 rows x 256 cols, batch). Loops 8 heads:
//   phase1: dw for head's 8 q-ch + 8 k-ch into smem
//   phase2: attn_partial parity-split accumulation from smem
// Q/K never touch gmem.
__global__ void __launch_bounds__(256) dwqk_attn(
    const float* __restrict__ q_dw_w, const float* __restrict__ k_dw_w)
{
    extern __shared__ float sm[];
    float* s_q   = sm;                 // [8][1024]
    float* s_k   = sm + 8192;          // [8][1024]
    float* s_dwq = sm + 16384;         // [64*9]
    float* s_dwk = sm + 16384 + 576;   // [64*9]
    float* s_red = sm + 16384 + 1152;  // [80*8]

    const int tid  = threadIdx.x;
    const int b    = blockIdx.y;
    const int tile = blockIdx.x;
    const int y0   = tile*4;

    for (int i = tid; i < 576; i += 256) { s_dwq[i] = q_dw_w[i]; s_dwk[i] = k_dw_w[i]; }

    const int cg = tid & 63, rowl = tid >> 6;     // phase1 mapping
    const int x4 = cg*4, y = y0 + rowl;
    const int lane = tid & 31, wrp = tid >> 5;
    const int parity = tid & 1, slot = tid >> 1;  // phase2 mapping

    const float* qmb = g_midQ + (size_t)b*(C*NPIX);
    const float* kmb = g_midK + (size_t)b*(C*NPIX);

    for (int h = 0; h < NHEADS; h++) {
        __syncthreads();   // smem free (also covers s_dw on first iter)

        // ---- phase 1: depthwise for 8 q-channels and 8 k-channels ----
        #pragma unroll
        for (int qk = 0; qk < 2; qk++) {
            const float* src = qk ? kmb : qmb;
            const float* dw  = qk ? s_dwk : s_dwq;
            float* dst       = qk ? s_k : s_q;
            #pragma unroll
            for (int j = 0; j < 8; j++) {
                const int c = h*8 + j;
                const float* ic = src + (size_t)c*NPIX;
                const float* wc = dw + c*9;
                float a0 = 0.f, a1 = 0.f, a2 = 0.f, a3 = 0.f;
                #pragma unroll
                for (int dy = -1; dy <= 1; dy++) {
                    const int yy = y + dy;
                    if (yy < 0 || yy >= HH) continue;
                    const float* row = ic + yy*WW;
                    const float4 m = *(const float4*)(row + x4);
                    const float l = (x4 > 0)      ? __ldg(row + x4 - 1) : 0.f;
                    const float r = (x4 + 4 < WW) ? __ldg(row + x4 + 4) : 0.f;
                    const float w0 = wc[(dy+1)*3], w1 = wc[(dy+1)*3+1], w2 = wc[(dy+1)*3+2];
                    a0 += w0*l   + w1*m.x + w2*m.y;
                    a1 += w0*m.x + w1*m.y + w2*m.z;
                    a2 += w0*m.y + w1*m.z + w2*m.w;
                    a3 += w0*m.z + w1*m.w + w2*r;
                }
                *(float4*)(dst + j*1024 + rowl*256 + x4) = make_float4(a0, a1, a2, a3);
            }
        }
        __syncthreads();

        // ---- phase 2: parity-split S/qs/ks accumulation over 1024 px ----
        float S[32], qs[4], ks[8];
        #pragma unroll
        for (int i = 0; i < 32; i++) S[i] = 0.f;
        #pragma unroll
        for (int i = 0; i < 4; i++) qs[i] = 0.f;
        #pragma unroll
        for (int i = 0; i < 8; i++) ks[i] = 0.f;

        const float* qp = s_q + parity*4*1024;
        #pragma unroll 2
        for (int it = 0; it < 8; it++) {
            const int n = it*128 + slot;
            float qv[4], kv[8];
            #pragma unroll
            for (int j = 0; j < 4; j++) qv[j] = qp[j*1024 + n];
            #pragma unroll
            for (int j = 0; j < 8; j++) kv[j] = s_k[j*1024 + n];
            #pragma unroll
            for (int c2 = 0; c2 < 4; c2++) {
                qs[c2] += qv[c2]*qv[c2];
                #pragma unroll
                for (int d = 0; d < 8; d++) S[c2*8 + d] += qv[c2]*kv[d];
            }
            #pragma unroll
            for (int d = 0; d < 8; d++) ks[d] += kv[d]*kv[d];
        }

        #pragma unroll
        for (int i = 0; i < 32; i++) {
            float v = S[i];
            #pragma unroll
            for (int o = 2; o <= 16; o <<= 1) v += __shfl_xor_sync(0xffffffffu, v, o);
            if (lane < 2) s_red[(i + 32*lane)*8 + wrp] = v;
        }
        #pragma unroll
        for (int i = 0; i < 4; i++) {
            float v = qs[i];
            #pragma unroll
            for (int o = 2; o <= 16; o <<= 1) v += __shfl_xor_sync(0xffffffffu, v, o);
            if (lane < 2) s_red[(64 + 4*lane + i)*8 + wrp] = v;
        }
        #pragma unroll
        for (int i = 0; i < 8; i++) {
            float v = ks[i];
            #pragma unroll
            for (int o = 1; o <= 16; o <<= 1) v += __shfl_xor_sync(0xffffffffu, v, o);
            if (lane == 0) s_red[(72 + i)*8 + wrp] = 0.5f*v;
        }
        __syncthreads();
        if (tid < 80) {
            float v = 0.f;
            #pragma unroll
            for (int w = 0; w < 8; w++) v += s_red[tid*8 + w];
            g_part[((b*NHEADS + h)*NTILE + tile)*80 + tid] = v;
        }
    }
}

// ---------------- depthwise 3x3 (V path only) ----------------------------------
__global__ void __launch_bounds__(256) dw3x3(
    const float* __restrict__ in, const float* __restrict__ w,
    float* __restrict__ out)
{
    const int z = blockIdx.z;
    const float* ib = in + (size_t)z*NPIX;
    float* ob = out + (size_t)z*NPIX;
    const float* wc = w + (z & (C-1))*9;

    const int tid = threadIdx.x;
    const int x4 = (tid & 63)*4;
    const int y  = blockIdx.y*4 + (tid >> 6);

    float wr[9];
    #pragma unroll
    for (int i = 0; i < 9; i++) wr[i] = __ldg(wc + i);

    float a0 = 0.f, a1 = 0.f, a2 = 0.f, a3 = 0.f;
    #pragma unroll
    for (int dy = -1; dy <= 1; dy++) {
        const int yy = y + dy;
        if (yy < 0 || yy >= HH) continue;
        const float* row = ib + yy*WW;
        const float4 m = *(const float4*)(row + x4);
        const float l = (x4 > 0)      ? __ldg(row + x4 - 1) : 0.f;
        const float r = (x4 + 4 < WW) ? __ldg(row + x4 + 4) : 0.f;
        const float w0 = wr[(dy+1)*3], w1 = wr[(dy+1)*3+1], w2 = wr[(dy+1)*3+2];
        a0 += w0*l   + w1*m.x + w2*m.y;
        a1 += w0*m.x + w1*m.y + w2*m.z;
        a2 += w0*m.y + w1*m.z + w2*m.w;
        a3 += w0*m.z + w1*m.w + w2*r;
    }
    *(float4*)(ob + y*WW + x4) = make_float4(a0, a1, a2, a3);
}

// ---------------- reduce partials, norms, softmax ------------------------------
__global__ void __launch_bounds__(128) attn_finalize(const float* __restrict__ temp)
{
    const int b = blockIdx.x >> 3, h = blockIdx.x & 7;
    const int tid = threadIdx.x;
    __shared__ float red[80];
    __shared__ float nq[8], nk[8];

    if (tid < 80) {
        float v = 0.f;
        const float* p = g_part + (b*NHEADS + h)*NTILE*80 + tid;
        #pragma unroll 8
        for (int ch = 0; ch < NTILE; ch++) v += p[ch*80];
        red[tid] = v;
    }
    __syncthreads();
    if (tid < 8)       nq[tid]   = fmaxf(sqrtf(red[64 + tid]),   1e-12f);
    else if (tid < 16) nk[tid-8] = fmaxf(sqrtf(red[72 + tid-8]), 1e-12f);
    __syncthreads();

    if (tid < 64) {
        const int c2 = tid >> 3, d = tid & 7;
        const float logit = red[c2*8 + d] / (nq[c2]*nk[d]) * temp[h];
        float m = logit;
        #pragma unroll
        for (int o = 4; o > 0; o >>= 1) m = fmaxf(m, __shfl_xor_sync(0xffffffffu, m, o, 8));
        const float e = expf(logit - m);
        float s = e;
        #pragma unroll
        for (int o = 4; o > 0; o >>= 1) s += __shfl_xor_sync(0xffffffffu, s, o, 8);
        g_attn[(b*NHEADS + h)*64 + tid] = e / s;
    }
}

// ---------------- W_eff[b] = proj_w @ blockdiag(attn[b]) ----------------------
__global__ void __launch_bounds__(256) compute_weff(const float* __restrict__ proj_w)
{
    const int b = blockIdx.x;
    __shared__ float s_attn[NHEADS*64];
    __shared__ float s_proj[C*C];
    const int tid = threadIdx.x;
    for (int i = tid; i < NHEADS*64; i += 256) s_attn[i] = g_attn[b*NHEADS*64 + i];
    for (int i = tid; i < C*C; i += 256)       s_proj[i] = proj_w[i];
    __syncthreads();
    for (int t = tid; t < C*C; t += 256) {
        const int co = t >> 6, cv = t & 63, hh = cv >> 3, d = cv & 7;
        float acc = 0.f;
        #pragma unroll
        for (int cp = 0; cp < 8; cp++)
            acc += s_proj[co*64 + hh*8 + cp] * s_attn[hh*64 + cp*8 + d];
        g_weff[b*C*C + t] = acc;
    }
}

// ---------------- launcher ----------------
extern "C" void kernel_launch(void* const* d_in, const int* in_sizes, int n_in,
                              void* d_out, int out_size)
{
    const float* input1      = (const float*)d_in[0];
    const float* input2      = (const float*)d_in[1];
    const float* q_w         = (const float*)d_in[2];
    const float* q_dw_w      = (const float*)d_in[3];
    const float* kv_w        = (const float*)d_in[4];
    const float* kv_dw_w     = (const float*)d_in[5];
    const float* proj_w      = (const float*)d_in[6];
    const float* temperature = (const float*)d_in[7];
    float* out = (float*)d_out;

    float* midQ; cudaGetSymbolAddress((void**)&midQ, g_midQ);
    float* midK; cudaGetSymbolAddress((void**)&midK, g_midK);
    float* midV; cudaGetSymbolAddress((void**)&midV, g_midV);
    float* V;    cudaGetSymbolAddress((void**)&V,    g_V);
    float* Weff; cudaGetSymbolAddress((void**)&Weff, g_weff);

    const int SMEM_G = 2 * 64 * PITCH * 4;            // 69632 B
    const int SMEM_A = (16384 + 1152 + 640) * 4;      // 72704 B
    cudaFuncSetAttribute(gemm_mma,    cudaFuncAttributeMaxDynamicSharedMemorySize, SMEM_G);
    cudaFuncSetAttribute(gemm_mma_kv, cudaFuncAttributeMaxDynamicSharedMemorySize, SMEM_G);
    cudaFuncSetAttribute(dwqk_attn,   cudaFuncAttributeMaxDynamicSharedMemorySize, SMEM_A);

    dim3 ggemm(NPIX/128, BATCH);
    dim3 gdw(1, HH/4, BATCH*C);
    dim3 gattn(NTILE, BATCH);

    gemm_mma<<<ggemm, 128, SMEM_G>>>(input1, q_w, midQ, 0);                 // 1
    gemm_mma_kv<<<ggemm, 256, SMEM_G>>>(input2, kv_w, midK, midV);          // 2
    dw3x3<<<gdw, 256>>>(midV, kv_dw_w + C*9, V);                            // 3
    dwqk_attn<<<gattn, 256, SMEM_A>>>(q_dw_w, kv_dw_w);                     // 4
    attn_finalize<<<BATCH*NHEADS, 128>>>(temperature);                      // 5
    compute_weff<<<BATCH, 256>>>(proj_w);                                   // 6
    gemm_mma<<<ggemm, 128, SMEM_G>>>(V, Weff, out, 1);                      // 7
}

// round 7
// speedup vs baseline: 1.1451x; 1.1451x over previous
#include <cuda_runtime.h>
#include <math.h>
#include <stdint.h>

#define BATCH 4
#define C 64
#define HH 256
#define WW 256
#define NPIX (HH*WW)
#define NHEADS 8
#define NTILE 64              // row tiles (4 rows each)
#define PITCH 136             // smem row pitch (floats) in gemm kernels

// ---------------- scratch (static device globals) ----------------
__device__ float g_midQ[BATCH*C*NPIX];
__device__ float g_midK[BATCH*C*NPIX];
__device__ float g_midV[BATCH*C*NPIX];
__device__ float g_V[BATCH*C*NPIX];
__device__ float g_part[BATCH*NHEADS*NTILE*80];
__device__ float g_attn[BATCH*NHEADS*64];
__device__ float g_weff[BATCH*C*C];

__device__ __forceinline__ uint32_t f2tf32(float v){
    uint32_t t; asm("cvt.rna.tf32.f32 %0, %1;" : "=r"(t) : "f"(v)); return t;
}

#define MMA_TF32(c0,c1,c2,c3,a0,a1,a2,a3,b0,b1) \
  asm volatile("mma.sync.aligned.m16n8k8.row.col.f32.tf32.tf32.f32 " \
    "{%0,%1,%2,%3}, {%4,%5,%6,%7}, {%8,%9}, {%0,%1,%2,%3};" \
    : "+f"(c0),"+f"(c1),"+f"(c2),"+f"(c3) \
    : "r"(a0),"r"(a1),"r"(a2),"r"(a3),"r"(b0),"r"(b1))

// ============ gemm_mma: out[co][px] = sum_ci w[co][ci]*in[ci][px], 64 out ch ===
__global__ void __launch_bounds__(128) gemm_mma(
    const float* __restrict__ in, const float* __restrict__ w,
    float* __restrict__ out, int w_per_batch)
{
    extern __shared__ float sm[];              // [2][64][PITCH]
    float* s_hi = sm;
    float* s_lo = sm + 64*PITCH;

    const int tid  = threadIdx.x;
    const int lane = tid & 31, warp = tid >> 5;
    const int b    = blockIdx.y;
    const int px0  = blockIdx.x * 128;
    const int gid  = lane >> 2, tig = lane & 3;

    const float* wb = w + (w_per_batch ? b*C*C : 0);
    uint32_t Ah[8][4], Al[8][4];
    const int co_r0 = warp*16 + gid;
    #pragma unroll
    for (int kc = 0; kc < 8; kc++) {
        #pragma unroll
        for (int j = 0; j < 4; j++) {
            const int row = co_r0 + (j & 1)*8;
            const int col = kc*8 + tig + (j >> 1)*4;
            const float x = __ldg(wb + row*C + col);
            const uint32_t h = f2tf32(x);
            Ah[kc][j] = h;
            Al[kc][j] = f2tf32(x - __uint_as_float(h));
        }
    }

    const float* ib = in + (size_t)b*(C*NPIX) + px0;
    #pragma unroll
    for (int i = 0; i < 16; i++) {
        const int ci = warp + 4*i;
        const float4 v = *(const float4*)(ib + (size_t)ci*NPIX + lane*4);
        uint32_t h0 = f2tf32(v.x), h1 = f2tf32(v.y);
        uint32_t h2 = f2tf32(v.z), h3 = f2tf32(v.w);
        uint32_t l0 = f2tf32(v.x - __uint_as_float(h0));
        uint32_t l1 = f2tf32(v.y - __uint_as_float(h1));
        uint32_t l2 = f2tf32(v.z - __uint_as_float(h2));
        uint32_t l3 = f2tf32(v.w - __uint_as_float(h3));
        *(uint4*)(s_hi + ci*PITCH + lane*4) = make_uint4(h0, h1, h2, h3);
        *(uint4*)(s_lo + ci*PITCH + lane*4) = make_uint4(l0, l1, l2, l3);
    }
    __syncthreads();

    float* ob = out + (size_t)b*(C*NPIX) + px0;
    const int co_base = warp*16;
    #pragma unroll 2
    for (int nt = 0; nt < 16; nt++) {
        float c0 = 0.f, c1 = 0.f, c2 = 0.f, c3 = 0.f;
        const int pxl = nt*8 + gid;
        #pragma unroll
        for (int kc = 0; kc < 8; kc++) {
            const int r0 = (kc*8 + tig)*PITCH + pxl;
            const int r1 = r0 + 4*PITCH;
            const uint32_t b0h = __float_as_uint(s_hi[r0]);
            const uint32_t b1h = __float_as_uint(s_hi[r1]);
            const uint32_t b0l = __float_as_uint(s_lo[r0]);
            const uint32_t b1l = __float_as_uint(s_lo[r1]);
            MMA_TF32(c0,c1,c2,c3, Ah[kc][0],Ah[kc][1],Ah[kc][2],Ah[kc][3], b0h,b1h);
            MMA_TF32(c0,c1,c2,c3, Ah[kc][0],Ah[kc][1],Ah[kc][2],Ah[kc][3], b0l,b1l);
            MMA_TF32(c0,c1,c2,c3, Al[kc][0],Al[kc][1],Al[kc][2],Al[kc][3], b0h,b1h);
        }
        const int pxs = nt*8 + tig*2;
        *(float2*)(ob + (size_t)(co_base+gid  )*NPIX + pxs) = make_float2(c0, c1);
        *(float2*)(ob + (size_t)(co_base+gid+8)*NPIX + pxs) = make_float2(c2, c3);
    }
}

// ======== gemm_mma_kv: 128 output channels (K then V), input staged once ======
__global__ void __launch_bounds__(256) gemm_mma_kv(
    const float* __restrict__ in, const float* __restrict__ w,
    float* __restrict__ outK, float* __restrict__ outV)
{
    extern __shared__ float sm[];
    float* s_hi = sm;
    float* s_lo = sm + 64*PITCH;

    const int tid  = threadIdx.x;
    const int lane = tid & 31, warp = tid >> 5;   // 8 warps
    const int b    = blockIdx.y;
    const int px0  = blockIdx.x * 128;
    const int gid  = lane >> 2, tig = lane & 3;

    uint32_t Ah[8][4], Al[8][4];
    const int co_r0 = warp*16 + gid;              // 0..127
    #pragma unroll
    for (int kc = 0; kc < 8; kc++) {
        #pragma unroll
        for (int j = 0; j < 4; j++) {
            const int row = co_r0 + (j & 1)*8;
            const int col = kc*8 + tig + (j >> 1)*4;
            const float x = __ldg(w + row*C + col);
            const uint32_t h = f2tf32(x);
            Ah[kc][j] = h;
            Al[kc][j] = f2tf32(x - __uint_as_float(h));
        }
    }

    const float* ib = in + (size_t)b*(C*NPIX) + px0;
    #pragma unroll
    for (int i = 0; i < 8; i++) {
        const int ci = warp + 8*i;
        const float4 v = *(const float4*)(ib + (size_t)ci*NPIX + lane*4);
        uint32_t h0 = f2tf32(v.x), h1 = f2tf32(v.y);
        uint32_t h2 = f2tf32(v.z), h3 = f2tf32(v.w);
        uint32_t l0 = f2tf32(v.x - __uint_as_float(h0));
        uint32_t l1 = f2tf32(v.y - __uint_as_float(h1));
        uint32_t l2 = f2tf32(v.z - __uint_as_float(h2));
        uint32_t l3 = f2tf32(v.w - __uint_as_float(h3));
        *(uint4*)(s_hi + ci*PITCH + lane*4) = make_uint4(h0, h1, h2, h3);
        *(uint4*)(s_lo + ci*PITCH + lane*4) = make_uint4(l0, l1, l2, l3);
    }
    __syncthreads();

    const int co_base = warp*16;                  // 0..112
    float* ob = ((co_base < 64) ? outK : outV) + (size_t)b*(C*NPIX) + px0;
    const int co_loc = co_base & 63;
    #pragma unroll 2
    for (int nt = 0; nt < 16; nt++) {
        float c0 = 0.f, c1 = 0.f, c2 = 0.f, c3 = 0.f;
        const int pxl = nt*8 + gid;
        #pragma unroll
        for (int kc = 0; kc < 8; kc++) {
            const int r0 = (kc*8 + tig)*PITCH + pxl;
            const int r1 = r0 + 4*PITCH;
            const uint32_t b0h = __float_as_uint(s_hi[r0]);
            const uint32_t b1h = __float_as_uint(s_hi[r1]);
            const uint32_t b0l = __float_as_uint(s_lo[r0]);
            const uint32_t b1l = __float_as_uint(s_lo[r1]);
            MMA_TF32(c0,c1,c2,c3, Ah[kc][0],Ah[kc][1],Ah[kc][2],Ah[kc][3], b0h,b1h);
            MMA_TF32(c0,c1,c2,c3, Ah[kc][0],Ah[kc][1],Ah[kc][2],Ah[kc][3], b0l,b1l);
            MMA_TF32(c0,c1,c2,c3, Al[kc][0],Al[kc][1],Al[kc][2],Al[kc][3], b0h,b1h);
        }
        const int pxs = nt*8 + tig*2;
        *(float2*)(ob + (size_t)(co_loc+gid  )*NPIX + pxs) = make_float2(c0, c1);
        *(float2*)(ob + (size_t)(co_loc+gid+8)*NPIX + pxs) = make_float2(c2, c3);
    }
}

// ============ dwqk_attn: one head per block, dw -> smem -> partial dots =======
// Block = (row-tile of 4 rows x 256 cols, head, batch) -> 2048 CTAs.
__global__ void __launch_bounds__(256) dwqk_attn(
    const float* __restrict__ q_dw_w, const float* __restrict__ k_dw_w)
{
    __shared__ float s_q[8*1024];
    __shared__ float s_k[8*1024];
    __shared__ float s_red[80*8];

    const int tid  = threadIdx.x;
    const int tile = blockIdx.x;
    const int h    = blockIdx.y;
    const int b    = blockIdx.z;
    const int y0   = tile*4;

    const int cg = tid & 63, rowl = tid >> 6;     // phase1 mapping
    const int x4 = cg*4, y = y0 + rowl;
    const int lane = tid & 31, wrp = tid >> 5;
    const int parity = tid & 1, slot = tid >> 1;  // phase2 mapping

    const float* qmb = g_midQ + (size_t)b*(C*NPIX);
    const float* kmb = g_midK + (size_t)b*(C*NPIX);

    // ---- phase 1: depthwise for 8 q-channels and 8 k-channels ----
    #pragma unroll
    for (int qk = 0; qk < 2; qk++) {
        const float* src = qk ? kmb : qmb;
        const float* dwb = (qk ? k_dw_w : q_dw_w) + h*8*9;
        float* dst       = qk ? s_k : s_q;
        #pragma unroll
        for (int j = 0; j < 8; j++) {
            const int c = h*8 + j;
            const float* ic = src + (size_t)c*NPIX;
            const float* wc = dwb + j*9;
            float wr[9];
            #pragma unroll
            for (int i = 0; i < 9; i++) wr[i] = __ldg(wc + i);
            float a0 = 0.f, a1 = 0.f, a2 = 0.f, a3 = 0.f;
            #pragma unroll
            for (int dy = -1; dy <= 1; dy++) {
                const int yy = y + dy;
                if (yy < 0 || yy >= HH) continue;
                const float* row = ic + yy*WW;
                const float4 m = *(const float4*)(row + x4);
                const float l = (x4 > 0)      ? __ldg(row + x4 - 1) : 0.f;
                const float r = (x4 + 4 < WW) ? __ldg(row + x4 + 4) : 0.f;
                const float w0 = wr[(dy+1)*3], w1 = wr[(dy+1)*3+1], w2 = wr[(dy+1)*3+2];
                a0 += w0*l   + w1*m.x + w2*m.y;
                a1 += w0*m.x + w1*m.y + w2*m.z;
                a2 += w0*m.y + w1*m.z + w2*m.w;
                a3 += w0*m.z + w1*m.w + w2*r;
            }
            *(float4*)(dst + j*1024 + rowl*256 + x4) = make_float4(a0, a1, a2, a3);
        }
    }
    __syncthreads();

    // ---- phase 2: parity-split S/qs/ks accumulation over 1024 px ----
    float S[32], qs[4], ks[8];
    #pragma unroll
    for (int i = 0; i < 32; i++) S[i] = 0.f;
    #pragma unroll
    for (int i = 0; i < 4; i++) qs[i] = 0.f;
    #pragma unroll
    for (int i = 0; i < 8; i++) ks[i] = 0.f;

    const float* qp = s_q + parity*4*1024;
    #pragma unroll 2
    for (int it = 0; it < 8; it++) {
        const int n = it*128 + slot;
        float qv[4], kv[8];
        #pragma unroll
        for (int j = 0; j < 4; j++) qv[j] = qp[j*1024 + n];
        #pragma unroll
        for (int j = 0; j < 8; j++) kv[j] = s_k[j*1024 + n];
        #pragma unroll
        for (int c2 = 0; c2 < 4; c2++) {
            qs[c2] += qv[c2]*qv[c2];
            #pragma unroll
            for (int d = 0; d < 8; d++) S[c2*8 + d] += qv[c2]*kv[d];
        }
        #pragma unroll
        for (int d = 0; d < 8; d++) ks[d] += kv[d]*kv[d];
    }

    #pragma unroll
    for (int i = 0; i < 32; i++) {
        float v = S[i];
        #pragma unroll
        for (int o = 2; o <= 16; o <<= 1) v += __shfl_xor_sync(0xffffffffu, v, o);
        if (lane < 2) s_red[(i + 32*lane)*8 + wrp] = v;
    }
    #pragma unroll
    for (int i = 0; i < 4; i++) {
        float v = qs[i];
        #pragma unroll
        for (int o = 2; o <= 16; o <<= 1) v += __shfl_xor_sync(0xffffffffu, v, o);
        if (lane < 2) s_red[(64 + 4*lane + i)*8 + wrp] = v;
    }
    #pragma unroll
    for (int i = 0; i < 8; i++) {
        float v = ks[i];
        #pragma unroll
        for (int o = 1; o <= 16; o <<= 1) v += __shfl_xor_sync(0xffffffffu, v, o);
        if (lane == 0) s_red[(72 + i)*8 + wrp] = 0.5f*v;
    }
    __syncthreads();
    if (tid < 80) {
        float v = 0.f;
        #pragma unroll
        for (int w = 0; w < 8; w++) v += s_red[tid*8 + w];
        g_part[((b*NHEADS + h)*NTILE + tile)*80 + tid] = v;
    }
}

// ---------------- depthwise 3x3 (V path only) ----------------------------------
__global__ void __launch_bounds__(256) dw3x3(
    const float* __restrict__ in, const float* __restrict__ w,
    float* __restrict__ out)
{
    const int z = blockIdx.z;
    const float* ib = in + (size_t)z*NPIX;
    float* ob = out + (size_t)z*NPIX;
    const float* wc = w + (z & (C-1))*9;

    const int tid = threadIdx.x;
    const int x4 = (tid & 63)*4;
    const int y  = blockIdx.y*4 + (tid >> 6);

    float wr[9];
    #pragma unroll
    for (int i = 0; i < 9; i++) wr[i] = __ldg(wc + i);

    float a0 = 0.f, a1 = 0.f, a2 = 0.f, a3 = 0.f;
    #pragma unroll
    for (int dy = -1; dy <= 1; dy++) {
        const int yy = y + dy;
        if (yy < 0 || yy >= HH) continue;
        const float* row = ib + yy*WW;
        const float4 m = *(const float4*)(row + x4);
        const float l = (x4 > 0)      ? __ldg(row + x4 - 1) : 0.f;
        const float r = (x4 + 4 < WW) ? __ldg(row + x4 + 4) : 0.f;
        const float w0 = wr[(dy+1)*3], w1 = wr[(dy+1)*3+1], w2 = wr[(dy+1)*3+2];
        a0 += w0*l   + w1*m.x + w2*m.y;
        a1 += w0*m.x + w1*m.y + w2*m.z;
        a2 += w0*m.y + w1*m.z + w2*m.w;
        a3 += w0*m.z + w1*m.w + w2*r;
    }
    *(float4*)(ob + y*WW + x4) = make_float4(a0, a1, a2, a3);
}

// ---------------- reduce partials, norms, softmax ------------------------------
__global__ void __launch_bounds__(128) attn_finalize(const float* __restrict__ temp)
{
    const int b = blockIdx.x >> 3, h = blockIdx.x & 7;
    const int tid = threadIdx.x;
    __shared__ float red[80];
    __shared__ float nq[8], nk[8];

    if (tid < 80) {
        float v = 0.f;
        const float* p = g_part + (b*NHEADS + h)*NTILE*80 + tid;
        #pragma unroll 8
        for (int ch = 0; ch < NTILE; ch++) v += p[ch*80];
        red[tid] = v;
    }
    __syncthreads();
    if (tid < 8)       nq[tid]   = fmaxf(sqrtf(red[64 + tid]),   1e-12f);
    else if (tid < 16) nk[tid-8] = fmaxf(sqrtf(red[72 + tid-8]), 1e-12f);
    __syncthreads();

    if (tid < 64) {
        const int c2 = tid >> 3, d = tid & 7;
        const float logit = red[c2*8 + d] / (nq[c2]*nk[d]) * temp[h];
        float m = logit;
        #pragma unroll
        for (int o = 4; o > 0; o >>= 1) m = fmaxf(m, __shfl_xor_sync(0xffffffffu, m, o, 8));
        const float e = expf(logit - m);
        float s = e;
        #pragma unroll
        for (int o = 4; o > 0; o >>= 1) s += __shfl_xor_sync(0xffffffffu, s, o, 8);
        g_attn[(b*NHEADS + h)*64 + tid] = e / s;
    }
}

// ---------------- W_eff[b] = proj_w @ blockdiag(attn[b]) ----------------------
__global__ void __launch_bounds__(256) compute_weff(const float* __restrict__ proj_w)
{
    const int b = blockIdx.x;
    __shared__ float s_attn[NHEADS*64];
    __shared__ float s_proj[C*C];
    const int tid = threadIdx.x;
    for (int i = tid; i < NHEADS*64; i += 256) s_attn[i] = g_attn[b*NHEADS*64 + i];
    for (int i = tid; i < C*C; i += 256)       s_proj[i] = proj_w[i];
    __syncthreads();
    for (int t = tid; t < C*C; t += 256) {
        const int co = t >> 6, cv = t & 63, hh = cv >> 3, d = cv & 7;
        float acc = 0.f;
        #pragma unroll
        for (int cp = 0; cp < 8; cp++)
            acc += s_proj[co*64 + hh*8 + cp] * s_attn[hh*64 + cp*8 + d];
        g_weff[b*C*C + t] = acc;
    }
}

// ---------------- launcher ----------------
extern "C" void kernel_launch(void* const* d_in, const int* in_sizes, int n_in,
                              void* d_out, int out_size)
{
    const float* input1      = (const float*)d_in[0];
    const float* input2      = (const float*)d_in[1];
    const float* q_w         = (const float*)d_in[2];
    const float* q_dw_w      = (const float*)d_in[3];
    const float* kv_w        = (const float*)d_in[4];
    const float* kv_dw_w     = (const float*)d_in[5];
    const float* proj_w      = (const float*)d_in[6];
    const float* temperature = (const float*)d_in[7];
    float* out = (float*)d_out;

    float* midQ; cudaGetSymbolAddress((void**)&midQ, g_midQ);
    float* midK; cudaGetSymbolAddress((void**)&midK, g_midK);
    float* midV; cudaGetSymbolAddress((void**)&midV, g_midV);
    float* V;    cudaGetSymbolAddress((void**)&V,    g_V);
    float* Weff; cudaGetSymbolAddress((void**)&Weff, g_weff);

    const int SMEM_G = 2 * 64 * PITCH * 4;            // 69632 B
    cudaFuncSetAttribute(gemm_mma,    cudaFuncAttributeMaxDynamicSharedMemorySize, SMEM_G);
    cudaFuncSetAttribute(gemm_mma_kv, cudaFuncAttributeMaxDynamicSharedMemorySize, SMEM_G);

    dim3 ghalf(NPIX/256, BATCH);                      // half-pixel-range grids
    dim3 ggemm(NPIX/128, BATCH);
    dim3 gdw(1, HH/4, BATCH*C);
    dim3 gattn(NTILE, NHEADS, BATCH);

    const int HALF = NPIX/2;

    // launches 1-5 split so #6 = dwqk_attn (ncu -s 5 -c 1 target)
    gemm_mma<<<ghalf, 128, SMEM_G>>>(input1, q_w, midQ, 0);                   // 1
    gemm_mma<<<ghalf, 128, SMEM_G>>>(input1 + HALF, q_w, midQ + HALF, 0);     // 2
    gemm_mma_kv<<<ghalf, 256, SMEM_G>>>(input2, kv_w, midK, midV);            // 3
    gemm_mma_kv<<<ghalf, 256, SMEM_G>>>(input2 + HALF, kv_w, midK + HALF, midV + HALF); // 4
    dw3x3<<<gdw, 256>>>(midV, kv_dw_w + C*9, V);                              // 5
    dwqk_attn<<<gattn, 256>>>(q_dw_w, kv_dw_w);                               // 6 <- profiled
    attn_finalize<<<BATCH*NHEADS, 128>>>(temperature);                        // 7
    compute_weff<<<BATCH, 256>>>(proj_w);                                     // 8
    gemm_mma<<<ggemm, 128, SMEM_G>>>(V, Weff, out, 1);                        // 9
}

// round 8
// speedup vs baseline: 1.4370x; 1.2549x over previous
#include <cuda_runtime.h>
#include <math.h>
#include <stdint.h>

#define BATCH 4
#define C 64
#define HH 256
#define WW 256
#define NPIX (HH*WW)
#define NHEADS 8
#define NTILE 64              // row tiles (4 rows each)
#define PITCHU 136            // uint32 smem pitch: bank = 8*pair + px, conflict-free

// ---------------- scratch (static device globals) ----------------
__device__ float g_midQ[BATCH*C*NPIX];
__device__ float g_midK[BATCH*C*NPIX];
__device__ float g_midV[BATCH*C*NPIX];
__device__ float g_V[BATCH*C*NPIX];
__device__ float g_part[BATCH*NHEADS*NTILE*80];
__device__ float g_attn[BATCH*NHEADS*64];
__device__ float g_weff[BATCH*C*C];

// ---------------- bf16 3-split helpers ----------------
__device__ __forceinline__ uint32_t rbf16(float x){   // bf16 bits (low 16), RN
    uint32_t b = __float_as_uint(x);
    return (b + 0x7FFFu + ((b >> 16) & 1u)) >> 16;
}
__device__ __forceinline__ void split2(float x0, float x1, uint32_t& hi, uint32_t& lo){
    const uint32_t h0 = rbf16(x0), h1 = rbf16(x1);
    hi = h0 | (h1 << 16);                              // lo half = even k
    const float r0 = x0 - __uint_as_float(h0 << 16);
    const float r1 = x1 - __uint_as_float(h1 << 16);
    asm("cvt.rn.bf16x2.f32 %0, %1, %2;" : "=r"(lo) : "f"(r1), "f"(r0));
}

#define MMA_BF16(c0,c1,c2,c3,a0,a1,a2,a3,b0,b1) \
  asm volatile("mma.sync.aligned.m16n8k16.row.col.f32.bf16.bf16.f32 " \
    "{%0,%1,%2,%3}, {%4,%5,%6,%7}, {%8,%9}, {%0,%1,%2,%3};" \
    : "+f"(c0),"+f"(c1),"+f"(c2),"+f"(c3) \
    : "r"(a0),"r"(a1),"r"(a2),"r"(a3),"r"(b0),"r"(b1))

// ============ gemm_bf16: out[co][px] = sum_ci w[co][ci]*in[ci][px], 64 out ch ==
// 128 thr = 4 warps; warp owns co tile [16w,16w+16). CTA = 128 px. bf16 3-split.
__global__ void __launch_bounds__(128) gemm_bf16(
    const float* __restrict__ in, const float* __restrict__ w,
    float* __restrict__ out, int w_per_batch)
{
    __shared__ uint32_t s_hi[32*PITCHU];   // [ci-pair][px]
    __shared__ uint32_t s_lo[32*PITCHU];

    const int tid  = threadIdx.x;
    const int lane = tid & 31, warp = tid >> 5;
    const int b    = blockIdx.y;
    const int px0  = blockIdx.x * 128;
    const int gid  = lane >> 2, tig = lane & 3;

    // weights: A[16co][64ci] -> 4 k16-chunks x 4 regs, hi/lo
    const float* wb = w + (w_per_batch ? b*C*C : 0);
    uint32_t Wh[4][4], Wl[4][4];
    #pragma unroll
    for (int kc = 0; kc < 4; kc++) {
        #pragma unroll
        for (int j = 0; j < 4; j++) {
            const int row = warp*16 + gid + (j & 1)*8;
            const int p   = 8*kc + tig + (j >> 1)*4;       // ci pair
            const float2 x = *(const float2*)(wb + row*C + 2*p);
            split2(x.x, x.y, Wh[kc][j], Wl[kc][j]);
        }
    }

    // stage X: pairs (2p,2p+1) packed bf16x2, hi+lo; warp handles 8 pairs
    const float* ib = in + (size_t)b*(C*NPIX) + px0;
    #pragma unroll
    for (int i = 0; i < 8; i++) {
        const int p = warp + 4*i;
        const float4 e = *(const float4*)(ib + (size_t)(2*p  )*NPIX + lane*4);
        const float4 o = *(const float4*)(ib + (size_t)(2*p+1)*NPIX + lane*4);
        uint32_t h0,l0,h1,l1,h2,l2,h3,l3;
        split2(e.x, o.x, h0, l0); split2(e.y, o.y, h1, l1);
        split2(e.z, o.z, h2, l2); split2(e.w, o.w, h3, l3);
        *(uint4*)(s_hi + p*PITCHU + lane*4) = make_uint4(h0,h1,h2,h3);
        *(uint4*)(s_lo + p*PITCHU + lane*4) = make_uint4(l0,l1,l2,l3);
    }
    __syncthreads();

    float* ob = out + (size_t)b*(C*NPIX) + px0;
    const int co_base = warp*16;
    #pragma unroll 2
    for (int nt = 0; nt < 16; nt++) {
        float c0 = 0.f, c1 = 0.f, c2 = 0.f, c3 = 0.f;
        const int pxl = nt*8 + gid;
        #pragma unroll
        for (int kc = 0; kc < 4; kc++) {
            const int r0 = (8*kc + tig)*PITCHU + pxl;
            const int r1 = r0 + 4*PITCHU;
            const uint32_t b0h = s_hi[r0], b1h = s_hi[r1];
            const uint32_t b0l = s_lo[r0], b1l = s_lo[r1];
            MMA_BF16(c0,c1,c2,c3, Wh[kc][0],Wh[kc][1],Wh[kc][2],Wh[kc][3], b0h,b1h);
            MMA_BF16(c0,c1,c2,c3, Wh[kc][0],Wh[kc][1],Wh[kc][2],Wh[kc][3], b0l,b1l);
            MMA_BF16(c0,c1,c2,c3, Wl[kc][0],Wl[kc][1],Wl[kc][2],Wl[kc][3], b0h,b1h);
        }
        const int pxs = nt*8 + tig*2;
        *(float2*)(ob + (size_t)(co_base+gid  )*NPIX + pxs) = make_float2(c0, c1);
        *(float2*)(ob + (size_t)(co_base+gid+8)*NPIX + pxs) = make_float2(c2, c3);
    }
}

// ======== gemm_bf16_kv: 128 out channels (K then V), input staged once ========
__global__ void __launch_bounds__(256) gemm_bf16_kv(
    const float* __restrict__ in, const float* __restrict__ w,
    float* __restrict__ outK, float* __restrict__ outV)
{
    __shared__ uint32_t s_hi[32*PITCHU];
    __shared__ uint32_t s_lo[32*PITCHU];

    const int tid  = threadIdx.x;
    const int lane = tid & 31, warp = tid >> 5;     // 8 warps
    const int b    = blockIdx.y;
    const int px0  = blockIdx.x * 128;
    const int gid  = lane >> 2, tig = lane & 3;

    uint32_t Wh[4][4], Wl[4][4];
    #pragma unroll
    for (int kc = 0; kc < 4; kc++) {
        #pragma unroll
        for (int j = 0; j < 4; j++) {
            const int row = warp*16 + gid + (j & 1)*8;   // 0..127
            const int p   = 8*kc + tig + (j >> 1)*4;
            const float2 x = *(const float2*)(w + row*C + 2*p);
            split2(x.x, x.y, Wh[kc][j], Wl[kc][j]);
        }
    }

    const float* ib = in + (size_t)b*(C*NPIX) + px0;
    #pragma unroll
    for (int i = 0; i < 4; i++) {
        const int p = warp + 8*i;
        const float4 e = *(const float4*)(ib + (size_t)(2*p  )*NPIX + lane*4);
        const float4 o = *(const float4*)(ib + (size_t)(2*p+1)*NPIX + lane*4);
        uint32_t h0,l0,h1,l1,h2,l2,h3,l3;
        split2(e.x, o.x, h0, l0); split2(e.y, o.y, h1, l1);
        split2(e.z, o.z, h2, l2); split2(e.w, o.w, h3, l3);
        *(uint4*)(s_hi + p*PITCHU + lane*4) = make_uint4(h0,h1,h2,h3);
        *(uint4*)(s_lo + p*PITCHU + lane*4) = make_uint4(l0,l1,l2,l3);
    }
    __syncthreads();

    const int co_base = warp*16;
    float* ob = ((co_base < 64) ? outK : outV) + (size_t)b*(C*NPIX) + px0;
    const int co_loc = co_base & 63;
    #pragma unroll 2
    for (int nt = 0; nt < 16; nt++) {
        float c0 = 0.f, c1 = 0.f, c2 = 0.f, c3 = 0.f;
        const int pxl = nt*8 + gid;
        #pragma unroll
        for (int kc = 0; kc < 4; kc++) {
            const int r0 = (8*kc + tig)*PITCHU + pxl;
            const int r1 = r0 + 4*PITCHU;
            const uint32_t b0h = s_hi[r0], b1h = s_hi[r1];
            const uint32_t b0l = s_lo[r0], b1l = s_lo[r1];
            MMA_BF16(c0,c1,c2,c3, Wh[kc][0],Wh[kc][1],Wh[kc][2],Wh[kc][3], b0h,b1h);
            MMA_BF16(c0,c1,c2,c3, Wh[kc][0],Wh[kc][1],Wh[kc][2],Wh[kc][3], b0l,b1l);
            MMA_BF16(c0,c1,c2,c3, Wl[kc][0],Wl[kc][1],Wl[kc][2],Wl[kc][3], b0h,b1h);
        }
        const int pxs = nt*8 + tig*2;
        *(float2*)(ob + (size_t)(co_loc+gid  )*NPIX + pxs) = make_float2(c0, c1);
        *(float2*)(ob + (size_t)(co_loc+gid+8)*NPIX + pxs) = make_float2(c2, c3);
    }
}

// ============ dwqk_attn: one head per block, dw -> smem -> partial dots =======
__global__ void __launch_bounds__(256) dwqk_attn(
    const float* __restrict__ q_dw_w, const float* __restrict__ k_dw_w)
{
    __shared__ float s_q[8*1024];
    __shared__ float s_k[8*1024];
    __shared__ float s_red[80*8];

    const int tid  = threadIdx.x;
    const int tile = blockIdx.x;
    const int h    = blockIdx.y;
    const int b    = blockIdx.z;
    const int y0   = tile*4;

    const int cg = tid & 63, rowl = tid >> 6;
    const int x4 = cg*4, y = y0 + rowl;
    const int lane = tid & 31, wrp = tid >> 5;
    const int parity = tid & 1, slot = tid >> 1;

    const float* qmb = g_midQ + (size_t)b*(C*NPIX);
    const float* kmb = g_midK + (size_t)b*(C*NPIX);

    #pragma unroll
    for (int qk = 0; qk < 2; qk++) {
        const float* src = qk ? kmb : qmb;
        const float* dwb = (qk ? k_dw_w : q_dw_w) + h*8*9;
        float* dst       = qk ? s_k : s_q;
        #pragma unroll
        for (int j = 0; j < 8; j++) {
            const int c = h*8 + j;
            const float* ic = src + (size_t)c*NPIX;
            const float* wc = dwb + j*9;
            float wr[9];
            #pragma unroll
            for (int i = 0; i < 9; i++) wr[i] = __ldg(wc + i);
            float a0 = 0.f, a1 = 0.f, a2 = 0.f, a3 = 0.f;
            #pragma unroll
            for (int dy = -1; dy <= 1; dy++) {
                const int yy = y + dy;
                if (yy < 0 || yy >= HH) continue;
                const float* row = ic + yy*WW;
                const float4 m = *(const float4*)(row + x4);
                const float l = (x4 > 0)      ? __ldg(row + x4 - 1) : 0.f;
                const float r = (x4 + 4 < WW) ? __ldg(row + x4 + 4) : 0.f;
                const float w0 = wr[(dy+1)*3], w1 = wr[(dy+1)*3+1], w2 = wr[(dy+1)*3+2];
                a0 += w0*l   + w1*m.x + w2*m.y;
                a1 += w0*m.x + w1*m.y + w2*m.z;
                a2 += w0*m.y + w1*m.z + w2*m.w;
                a3 += w0*m.z + w1*m.w + w2*r;
            }
            *(float4*)(dst + j*1024 + rowl*256 + x4) = make_float4(a0, a1, a2, a3);
        }
    }
    __syncthreads();

    float S[32], qs[4], ks[8];
    #pragma unroll
    for (int i = 0; i < 32; i++) S[i] = 0.f;
    #pragma unroll
    for (int i = 0; i < 4; i++) qs[i] = 0.f;
    #pragma unroll
    for (int i = 0; i < 8; i++) ks[i] = 0.f;

    const float* qp = s_q + parity*4*1024;
    #pragma unroll 2
    for (int it = 0; it < 8; it++) {
        const int n = it*128 + slot;
        float qv[4], kv[8];
        #pragma unroll
        for (int j = 0; j < 4; j++) qv[j] = qp[j*1024 + n];
        #pragma unroll
        for (int j = 0; j < 8; j++) kv[j] = s_k[j*1024 + n];
        #pragma unroll
        for (int c2 = 0; c2 < 4; c2++) {
            qs[c2] += qv[c2]*qv[c2];
            #pragma unroll
            for (int d = 0; d < 8; d++) S[c2*8 + d] += qv[c2]*kv[d];
        }
        #pragma unroll
        for (int d = 0; d < 8; d++) ks[d] += kv[d]*kv[d];
    }

    #pragma unroll
    for (int i = 0; i < 32; i++) {
        float v = S[i];
        #pragma unroll
        for (int o = 2; o <= 16; o <<= 1) v += __shfl_xor_sync(0xffffffffu, v, o);
        if (lane < 2) s_red[(i + 32*lane)*8 + wrp] = v;
    }
    #pragma unroll
    for (int i = 0; i < 4; i++) {
        float v = qs[i];
        #pragma unroll
        for (int o = 2; o <= 16; o <<= 1) v += __shfl_xor_sync(0xffffffffu, v, o);
        if (lane < 2) s_red[(64 + 4*lane + i)*8 + wrp] = v;
    }
    #pragma unroll
    for (int i = 0; i < 8; i++) {
        float v = ks[i];
        #pragma unroll
        for (int o = 1; o <= 16; o <<= 1) v += __shfl_xor_sync(0xffffffffu, v, o);
        if (lane == 0) s_red[(72 + i)*8 + wrp] = 0.5f*v;
    }
    __syncthreads();
    if (tid < 80) {
        float v = 0.f;
        #pragma unroll
        for (int w = 0; w < 8; w++) v += s_red[tid*8 + w];
        g_part[((b*NHEADS + h)*NTILE + tile)*80 + tid] = v;
    }
}

// ---------------- depthwise 3x3 (V path only) ----------------------------------
__global__ void __launch_bounds__(256) dw3x3(
    const float* __restrict__ in, const float* __restrict__ w,
    float* __restrict__ out)
{
    const int z = blockIdx.z;
    const float* ib = in + (size_t)z*NPIX;
    float* ob = out + (size_t)z*NPIX;
    const float* wc = w + (z & (C-1))*9;

    const int tid = threadIdx.x;
    const int x4 = (tid & 63)*4;
    const int y  = blockIdx.y*4 + (tid >> 6);

    float wr[9];
    #pragma unroll
    for (int i = 0; i < 9; i++) wr[i] = __ldg(wc + i);

    float a0 = 0.f, a1 = 0.f, a2 = 0.f, a3 = 0.f;
    #pragma unroll
    for (int dy = -1; dy <= 1; dy++) {
        const int yy = y + dy;
        if (yy < 0 || yy >= HH) continue;
        const float* row = ib + yy*WW;
        const float4 m = *(const float4*)(row + x4);
        const float l = (x4 > 0)      ? __ldg(row + x4 - 1) : 0.f;
        const float r = (x4 + 4 < WW) ? __ldg(row + x4 + 4) : 0.f;
        const float w0 = wr[(dy+1)*3], w1 = wr[(dy+1)*3+1], w2 = wr[(dy+1)*3+2];
        a0 += w0*l   + w1*m.x + w2*m.y;
        a1 += w0*m.x + w1*m.y + w2*m.z;
        a2 += w0*m.y + w1*m.z + w2*m.w;
        a3 += w0*m.z + w1*m.w + w2*r;
    }
    *(float4*)(ob + y*WW + x4) = make_float4(a0, a1, a2, a3);
}

// ---------------- reduce partials, norms, softmax ------------------------------
__global__ void __launch_bounds__(128) attn_finalize(const float* __restrict__ temp)
{
    const int b = blockIdx.x >> 3, h = blockIdx.x & 7;
    const int tid = threadIdx.x;
    __shared__ float red[80];
    __shared__ float nq[8], nk[8];

    if (tid < 80) {
        float v = 0.f;
        const float* p = g_part + (b*NHEADS + h)*NTILE*80 + tid;
        #pragma unroll 8
        for (int ch = 0; ch < NTILE; ch++) v += p[ch*80];
        red[tid] = v;
    }
    __syncthreads();
    if (tid < 8)       nq[tid]   = fmaxf(sqrtf(red[64 + tid]),   1e-12f);
    else if (tid < 16) nk[tid-8] = fmaxf(sqrtf(red[72 + tid-8]), 1e-12f);
    __syncthreads();

    if (tid < 64) {
        const int c2 = tid >> 3, d = tid & 7;
        const float logit = red[c2*8 + d] / (nq[c2]*nk[d]) * temp[h];
        float m = logit;
        #pragma unroll
        for (int o = 4; o > 0; o >>= 1) m = fmaxf(m, __shfl_xor_sync(0xffffffffu, m, o, 8));
        const float e = expf(logit - m);
        float s = e;
        #pragma unroll
        for (int o = 4; o > 0; o >>= 1) s += __shfl_xor_sync(0xffffffffu, s, o, 8);
        g_attn[(b*NHEADS + h)*64 + tid] = e / s;
    }
}

// ---------------- W_eff[b] = proj_w @ blockdiag(attn[b]) ----------------------
__global__ void __launch_bounds__(256) compute_weff(const float* __restrict__ proj_w)
{
    const int b = blockIdx.x;
    __shared__ float s_attn[NHEADS*64];
    __shared__ float s_proj[C*C];
    const int tid = threadIdx.x;
    for (int i = tid; i < NHEADS*64; i += 256) s_attn[i] = g_attn[b*NHEADS*64 + i];
    for (int i = tid; i < C*C; i += 256)       s_proj[i] = proj_w[i];
    __syncthreads();
    for (int t = tid; t < C*C; t += 256) {
        const int co = t >> 6, cv = t & 63, hh = cv >> 3, d = cv & 7;
        float acc = 0.f;
        #pragma unroll
        for (int cp = 0; cp < 8; cp++)
            acc += s_proj[co*64 + hh*8 + cp] * s_attn[hh*64 + cp*8 + d];
        g_weff[b*C*C + t] = acc;
    }
}

// ---------------- launcher ----------------
extern "C" void kernel_launch(void* const* d_in, const int* in_sizes, int n_in,
                              void* d_out, int out_size)
{
    const float* input1      = (const float*)d_in[0];
    const float* input2      = (const float*)d_in[1];
    const float* q_w         = (const float*)d_in[2];
    const float* q_dw_w      = (const float*)d_in[3];
    const float* kv_w        = (const float*)d_in[4];
    const float* kv_dw_w     = (const float*)d_in[5];
    const float* proj_w      = (const float*)d_in[6];
    const float* temperature = (const float*)d_in[7];
    float* out = (float*)d_out;

    float* midQ; cudaGetSymbolAddress((void**)&midQ, g_midQ);
    float* midK; cudaGetSymbolAddress((void**)&midK, g_midK);
    float* midV; cudaGetSymbolAddress((void**)&midV, g_midV);
    float* V;    cudaGetSymbolAddress((void**)&V,    g_V);
    float* Weff; cudaGetSymbolAddress((void**)&Weff, g_weff);

    dim3 ggemm(NPIX/128, BATCH);                 // (512, 4)
    dim3 gdw(1, HH/4, BATCH*C);
    dim3 gattn(NTILE, NHEADS, BATCH);

    gemm_bf16<<<ggemm, 128>>>(input1, q_w, midQ, 0);              // 1
    gemm_bf16_kv<<<ggemm, 256>>>(input2, kv_w, midK, midV);       // 2
    dw3x3<<<gdw, 256>>>(midV, kv_dw_w + C*9, V);                  // 3
    dwqk_attn<<<gattn, 256>>>(q_dw_w, kv_dw_w);                   // 4
    attn_finalize<<<BATCH*NHEADS, 128>>>(temperature);            // 5
    compute_weff<<<BATCH, 256>>>(proj_w);                         // 6
    gemm_bf16<<<ggemm, 128>>>(V, Weff, out, 1);                   // 7
}